// round 14
// baseline (speedup 1.0000x reference)
#include <cuda_runtime.h>
#include <stdint.h>
#include <math.h>

// ---------------- problem dims ----------------
#define NFEAT  6
#define PAIRS  15
#define EMBED  256
#define TOKENS 16384          // B*S
#define KCAT   512            // 2*EMBED

// ---------------- CTA tiling ----------------
// grid = TOKENS/128 = 128 CTAs (1 wave), 256 threads (8 warps), warp grid 2x4
// warp tile 64x64: 4 m16 x 8 n8 of m16n8k8 tf32 mma.
// B fed via cp.async (raw fp32 -> HW tf32 RZ truncation) to keep regs < 255.
#define BM 128
#define BN 256
#define BK 16

// ---------------- smem layout (u32 units) ----------------
#define ASTR 136              // A/H k-row stride (128 cols + 8 pad)
#define BSTR 264              // B k-row stride (256 cols + 8 pad)
#define AS_BUF (BK * ASTR)    // 2176 u32
#define BS_BUF (BK * BSTR)    // 4224 u32
#define OFF_AS 0
#define OFF_BS (2 * AS_BUF)                 // 4352
#define OFF_HS (OFF_BS + 2 * BS_BUF)        // 4352 + 8448 = 12800
#define SMEM_U32 (OFF_HS + 256 * ASTR)      // 12800 + 34816 = 47616
#define SMEM_BYTES (SMEM_U32 * 4)           // 190464 B (1 CTA/SM)

#define NT_S1 32              // stage-1 k-tiles (K=512)
#define NT_ALL 48             // + 16 stage-2 k-tiles (K=256)

__constant__ int c_pi[PAIRS] = {0,0,0,0,0,1,1,1,1,2,2,2,3,3,4};
__constant__ int c_pj[PAIRS] = {1,2,3,4,5,2,3,4,5,3,4,5,4,5,5};

// ---------------- helpers ----------------
__device__ __forceinline__ uint32_t f2tf(float x) {
    uint32_t u; asm("cvt.rn.tf32.f32 %0, %1;" : "=r"(u) : "f"(x)); return u;
}
__device__ __forceinline__ float fast_tanh(float x) {
    float ax = fabsf(x);
    float e; asm("ex2.approx.f32 %0, %1;" : "=f"(e) : "f"(-2.8853900817779268f * ax));
    float d; asm("rcp.approx.f32 %0, %1;" : "=f"(d) : "f"(1.0f + e));
    float t = (1.0f - e) * d;
    return copysignf(t, x);
}
__device__ __forceinline__ uint32_t smem_u32(const void* p) {
    uint32_t a;
    asm("{ .reg .u64 t; cvta.to.shared.u64 t, %1; cvt.u32.u64 %0, t; }" : "=r"(a) : "l"(p));
    return a;
}
__device__ __forceinline__ void mma_tf32(float* c, const uint32_t* a, const uint32_t* b) {
    asm volatile(
        "mma.sync.aligned.m16n8k8.row.col.f32.tf32.tf32.f32 "
        "{%0,%1,%2,%3}, {%4,%5,%6,%7}, {%8,%9}, {%0,%1,%2,%3};\n"
        : "+f"(c[0]), "+f"(c[1]), "+f"(c[2]), "+f"(c[3])
        : "r"(a[0]), "r"(a[1]), "r"(a[2]), "r"(a[3]), "r"(b[0]), "r"(b[1]));
}
__device__ __forceinline__ int pair_active(int p, const int* __restrict__ NAS) {
    const int fi = c_pi[p], fj = c_pj[p];
    return ((fi < 2) ? 1 : NAS[fi]) * ((fj < 2) ? 1 : NAS[fj]);
}

#define CP16(dst, src) asm volatile("cp.async.cg.shared.global [%0], [%1], 16;" :: "r"(dst), "l"(src))
#define CP_COMMIT()    asm volatile("cp.async.commit_group;" ::: "memory")
#define CP_WAIT0()     asm volatile("cp.async.wait_group 0;" ::: "memory")

// One BK=16 tile: 2 k8 blocks. Warp tile 64x64 (4 mi x 8 ni) -> 64 MMAs.
// A rows stride ASTR, cols swizzled: col' = (m + 2*(k&12)) & 127. B plain rows.
__device__ __forceinline__ void tile_mma(const uint32_t* __restrict__ bufA,
                                         const uint32_t* __restrict__ bufB,
                                         int tig, int g, int wm, int wn,
                                         float acc[4][8][4]) {
    #pragma unroll
    for (int ks8 = 0; ks8 < 2; ks8++) {
        const int ks = ks8 * 8;
        const uint32_t* Ak0 = bufA + (ks + tig) * ASTR;
        const uint32_t* Ak4 = bufA + (ks + tig + 4) * ASTR;
        const int o0 = (ks & 12) << 1;
        const int o4 = ((ks + 4) & 12) << 1;
        uint32_t a[4][4];
        #pragma unroll
        for (int mi = 0; mi < 4; mi++) {
            const int m = wm + mi * 16 + g;
            a[mi][0] = Ak0[(m + o0) & 127];
            a[mi][1] = Ak0[(m + 8 + o0) & 127];
            a[mi][2] = Ak4[(m + o4) & 127];
            a[mi][3] = Ak4[(m + 8 + o4) & 127];
        }
        const uint32_t* Bk0 = bufB + (ks + tig) * BSTR + wn + g;
        const uint32_t* Bk4 = bufB + (ks + tig + 4) * BSTR + wn + g;
        uint32_t b[8][2];
        #pragma unroll
        for (int ni = 0; ni < 8; ni++) { b[ni][0] = Bk0[ni * 8]; b[ni][1] = Bk4[ni * 8]; }
        #pragma unroll
        for (int mi = 0; mi < 4; mi++)
            #pragma unroll
            for (int ni = 0; ni < 8; ni++)
                mma_tf32(acc[mi][ni], a[mi], b[ni]);
    }
}

// ---------------- fused kernel ----------------
__global__ __launch_bounds__(256, 1) void fused_kernel(
    const float* __restrict__ features,
    const float* __restrict__ W_pair,
    const float* __restrict__ b_pair,
    const float* __restrict__ W_final,
    const float* __restrict__ b_final,
    const int* __restrict__ NAS,
    float* __restrict__ out)
{
    extern __shared__ uint32_t sm[];
    uint32_t* const smA = sm + OFF_AS;
    uint32_t* const smB = sm + OFF_BS;
    uint32_t* const Hs  = sm + OFF_HS;
    const uint32_t smB_addr = smem_u32(smB);

    const int tid = threadIdx.x;
    const int lane = tid & 31, wid = tid >> 5;
    const int g = lane >> 2, tig = lane & 3;
    const int wm = (wid >> 2) * 64;     // 2 m-blocks
    const int wn = (wid & 3) * 64;      // 4 n-blocks
    const int row0 = blockIdx.x * BM;

    // A loader: 128 rows x 16 k; thread -> row=tid>>1, 8 consecutive k at kc
    const int a_row = tid >> 1;            // 0..127
    const int a_kc  = (tid & 1) * 8;       // 0 or 8
    const int a_c0  = (a_row + 2 * a_kc) & 127;
    const int a_c1  = (a_c0 + 8) & 127;

    // B loader (cp.async): 16 rows x 256 floats; thread -> row=tid>>4, 64B
    const int b_row  = tid >> 4;           // 0..15
    const int b_fcol = (tid & 15) * 16;
    const uint32_t b_dst = (uint32_t)(b_row * BSTR + b_fcol) * 4u;

#define LOAD_A(Ab, kt) do { \
        const float* s_ = (Ab) + (size_t)a_row * EMBED + (kt) * 16 + a_kc; \
        av0 = *(const float4*)s_; \
        av1 = *(const float4*)(s_ + 4); \
    } while (0)
#define STORE_A(bufp) do { \
        uint32_t* d_ = (bufp) + a_kc * ASTR; \
        d_[0 * ASTR + a_c0] = f2tf(av0.x); d_[1 * ASTR + a_c0] = f2tf(av0.y); \
        d_[2 * ASTR + a_c0] = f2tf(av0.z); d_[3 * ASTR + a_c0] = f2tf(av0.w); \
        d_[4 * ASTR + a_c1] = f2tf(av1.x); d_[5 * ASTR + a_c1] = f2tf(av1.y); \
        d_[6 * ASTR + a_c1] = f2tf(av1.z); d_[7 * ASTR + a_c1] = f2tf(av1.w); \
    } while (0)
#define ISSUE_B(srcbase, buf) do { \
        const float* s_ = (srcbase) + (size_t)b_row * EMBED + b_fcol; \
        uint32_t d_ = smB_addr + (buf) * (BS_BUF * 4u) + b_dst; \
        CP16(d_, s_); CP16(d_ + 16, s_ + 4); \
        CP16(d_ + 32, s_ + 8); CP16(d_ + 48, s_ + 12); \
        CP_COMMIT(); \
    } while (0)

    float acc[4][8][4];
    bool first = true;

    #pragma unroll 1
    for (int p = 0; p < PAIRS; p++) {
        if (!pair_active(p, NAS)) continue;
        const int fi = c_pi[p], fj = c_pj[p];
        const float* Ai = features + ((size_t)fi * TOKENS + row0) * EMBED;
        const float* Aj = features + ((size_t)fj * TOKENS + row0) * EMBED;
        const float* Wp = W_pair + (size_t)p * KCAT * EMBED;
        const float* Wf = W_final + (size_t)p * EMBED * EMBED;

        #pragma unroll
        for (int mi = 0; mi < 4; mi++)
            #pragma unroll
            for (int ni = 0; ni < 8; ni++)
                #pragma unroll
                for (int r = 0; r < 4; r++) acc[mi][ni][r] = 0.f;

        float4 av0, av1;

        // ---- prologue: B tile0 via cp.async; A tile0 store; preload A tile1 ----
        ISSUE_B(Wp, 0);
        LOAD_A(Ai, 0);
        STORE_A(smA);
        LOAD_A(Ai, 1);
        CP_WAIT0();
        __syncthreads();

        // ---- 48 k-tiles: stage1 (0..31, A from smA) + stage2 (32..47, A from Hs) ----
        #pragma unroll 1
        for (int t = 0; t < NT_ALL; t++) {
            // issue next B tile first so the DMA overlaps this tile's MMAs
            if (t + 1 < NT_ALL) {
                const int u = t + 1;
                const float* src = (u < NT_S1) ? (Wp + (size_t)u * 16 * EMBED)
                                               : (Wf + (size_t)(u - NT_S1) * 16 * EMBED);
                ISSUE_B(src, u & 1);
            }
            const uint32_t* bufA = (t < NT_S1) ? (smA + (t & 1) * AS_BUF)
                                               : (Hs + (t - NT_S1) * AS_BUF);
            tile_mma(bufA, smB + (t & 1) * BS_BUF, tig, g, wm, wn, acc);

            if (t + 1 < NT_S1) {
                STORE_A(smA + ((t + 1) & 1) * AS_BUF);
                if (t + 2 < NT_S1) {
                    const int u2 = t + 2;
                    const float* Ab = (u2 < 16) ? Ai : Aj;
                    LOAD_A(Ab, u2 & 15);
                }
            }
            CP_WAIT0();
            __syncthreads();

            if (t == NT_S1 - 1) {
                // ---- epilogue 1: tanh -> tf32 RN -> Hs (stage-2 A layout) ----
                #pragma unroll
                for (int ni = 0; ni < 8; ni++) {
                    const int c = wn + ni * 8 + tig * 2;
                    const float2 bb = *(const float2*)&b_pair[p * EMBED + c];
                    const int sw = (c & 12) << 1;
                    #pragma unroll
                    for (int mi = 0; mi < 4; mi++) {
                        const int r0 = wm + mi * 16 + g, r1 = r0 + 8;
                        Hs[(c    ) * ASTR + ((r0 + sw) & 127)] = f2tf(fast_tanh(acc[mi][ni][0] + bb.x));
                        Hs[(c + 1) * ASTR + ((r0 + sw) & 127)] = f2tf(fast_tanh(acc[mi][ni][1] + bb.y));
                        Hs[(c    ) * ASTR + ((r1 + sw) & 127)] = f2tf(fast_tanh(acc[mi][ni][2] + bb.x));
                        Hs[(c + 1) * ASTR + ((r1 + sw) & 127)] = f2tf(fast_tanh(acc[mi][ni][3] + bb.y));
                    }
                }
                #pragma unroll
                for (int mi = 0; mi < 4; mi++)
                    #pragma unroll
                    for (int ni = 0; ni < 8; ni++)
                        #pragma unroll
                        for (int r = 0; r < 4; r++) acc[mi][ni][r] = 0.f;
                __syncthreads();
            }
        }

        // ---- epilogue 2 (per pair): out = / += acc (+ b_final on first) ----
        #pragma unroll
        for (int ni = 0; ni < 8; ni++) {
            const int c = wn + ni * 8 + tig * 2;
            const float2 bb = *(const float2*)&b_final[c];
            #pragma unroll
            for (int mi = 0; mi < 4; mi++) {
                const int r0 = row0 + wm + mi * 16 + g, r1 = r0 + 8;
                float2* o0 = (float2*)&out[(size_t)r0 * EMBED + c];
                float2* o1 = (float2*)&out[(size_t)r1 * EMBED + c];
                float2 v0 = make_float2(acc[mi][ni][0], acc[mi][ni][1]);
                float2 v1 = make_float2(acc[mi][ni][2], acc[mi][ni][3]);
                if (first) {
                    v0.x += bb.x; v0.y += bb.y;
                    v1.x += bb.x; v1.y += bb.y;
                } else {
                    float2 p0 = *o0, p1 = *o1;
                    v0.x += p0.x; v0.y += p0.y;
                    v1.x += p1.x; v1.y += p1.y;
                }
                *o0 = v0;
                *o1 = v1;
            }
        }
        first = false;
    }
#undef LOAD_A
#undef STORE_A
#undef ISSUE_B
}

// ---------------- launch ----------------
extern "C" void kernel_launch(void* const* d_in, const int* in_sizes, int n_in,
                              void* d_out, int out_size) {
    const float* features = (const float*)d_in[0];
    const float* W_pair   = (const float*)d_in[1];
    const float* b_pair   = (const float*)d_in[2];
    const float* W_final  = (const float*)d_in[3];
    const float* b_final  = (const float*)d_in[4];
    const int*   NAS      = (const int*)d_in[5];
    float* out = (float*)d_out;

    static int attr_set = 0;
    if (!attr_set) {
        cudaFuncSetAttribute(fused_kernel, cudaFuncAttributeMaxDynamicSharedMemorySize,
                             SMEM_BYTES);
        attr_set = 1;
    }

    fused_kernel<<<TOKENS / BM, 256, SMEM_BYTES>>>(
        features, W_pair, b_pair, W_final, b_final, NAS, out);
}

// round 15
// speedup vs baseline: 1.5059x; 1.5059x over previous
#include <cuda_runtime.h>
#include <stdint.h>
#include <math.h>

// ---------------- problem dims ----------------
#define NFEAT  6
#define PAIRS  15
#define EMBED  256
#define TOKENS 16384          // B*S
#define KCAT   512            // 2*EMBED

// ---------------- CTA tiling ----------------
// grid = TOKENS/128 = 128 CTAs (1 wave), 256 threads (8 warps), warp grid 2x4
// warp tile 64x64: 4 m16 x 8 n8 of m16n8k8 tf32 mma.
// B via cp.async, 3 buffers, wait_group 1 -> tile t+1 in flight during mma(t).
#define BM 128
#define BN 256
#define BK 16

// ---------------- smem layout (u32 units) ----------------
#define ASTR 136              // A/H k-row stride (128 cols + 8 pad)
#define BSTR 264              // B k-row stride (256 cols + 8 pad)
#define AS_BUF (BK * ASTR)    // 2176 u32
#define BS_BUF (BK * BSTR)    // 4224 u32
#define NBUF_B 3
#define OFF_AS 0
#define OFF_BS (2 * AS_BUF)                 // 4352
#define OFF_HS (OFF_BS + NBUF_B * BS_BUF)   // 4352 + 12672 = 17024
#define SMEM_U32 (OFF_HS + 256 * ASTR)      // 17024 + 34816 = 51840
#define SMEM_BYTES (SMEM_U32 * 4)           // 207360 B (1 CTA/SM)

#define NT_S1 32              // stage-1 k-tiles (K=512)
#define NT_ALL 48             // + 16 stage-2 k-tiles (K=256)

__constant__ int c_pi[PAIRS] = {0,0,0,0,0,1,1,1,1,2,2,2,3,3,4};
__constant__ int c_pj[PAIRS] = {1,2,3,4,5,2,3,4,5,3,4,5,4,5,5};

// ---------------- helpers ----------------
__device__ __forceinline__ uint32_t f2tf(float x) {
    uint32_t u; asm("cvt.rn.tf32.f32 %0, %1;" : "=r"(u) : "f"(x)); return u;
}
__device__ __forceinline__ float fast_tanh(float x) {
    float ax = fabsf(x);
    float e; asm("ex2.approx.f32 %0, %1;" : "=f"(e) : "f"(-2.8853900817779268f * ax));
    float d; asm("rcp.approx.f32 %0, %1;" : "=f"(d) : "f"(1.0f + e));
    float t = (1.0f - e) * d;
    return copysignf(t, x);
}
__device__ __forceinline__ uint32_t smem_u32(const void* p) {
    uint32_t a;
    asm("{ .reg .u64 t; cvta.to.shared.u64 t, %1; cvt.u32.u64 %0, t; }" : "=r"(a) : "l"(p));
    return a;
}
__device__ __forceinline__ void mma_tf32(float* c, const uint32_t* a, const uint32_t* b) {
    asm volatile(
        "mma.sync.aligned.m16n8k8.row.col.f32.tf32.tf32.f32 "
        "{%0,%1,%2,%3}, {%4,%5,%6,%7}, {%8,%9}, {%0,%1,%2,%3};\n"
        : "+f"(c[0]), "+f"(c[1]), "+f"(c[2]), "+f"(c[3])
        : "r"(a[0]), "r"(a[1]), "r"(a[2]), "r"(a[3]), "r"(b[0]), "r"(b[1]));
}
__device__ __forceinline__ int pair_active(int p, const int* __restrict__ NAS) {
    const int fi = c_pi[p], fj = c_pj[p];
    return ((fi < 2) ? 1 : NAS[fi]) * ((fj < 2) ? 1 : NAS[fj]);
}

#define CP16(dst, src) asm volatile("cp.async.cg.shared.global [%0], [%1], 16;" :: "r"(dst), "l"(src))
#define CP_COMMIT()    asm volatile("cp.async.commit_group;" ::: "memory")
#define CP_WAIT1()     asm volatile("cp.async.wait_group 1;" ::: "memory")
#define CP_WAIT0()     asm volatile("cp.async.wait_group 0;" ::: "memory")

// One BK=16 tile: 2 k8 blocks. Warp tile 64x64 (4 mi x 8 ni) -> 64 MMAs.
// A rows stride ASTR, cols swizzled: col' = (m + 2*(k&12)) & 127. B plain rows.
__device__ __forceinline__ void tile_mma(const uint32_t* __restrict__ bufA,
                                         const uint32_t* __restrict__ bufB,
                                         int tig, int g, int wm, int wn,
                                         float acc[4][8][4]) {
    #pragma unroll
    for (int ks8 = 0; ks8 < 2; ks8++) {
        const int ks = ks8 * 8;
        const uint32_t* Ak0 = bufA + (ks + tig) * ASTR;
        const uint32_t* Ak4 = bufA + (ks + tig + 4) * ASTR;
        const int o0 = (ks & 12) << 1;
        const int o4 = ((ks + 4) & 12) << 1;
        uint32_t a[4][4];
        #pragma unroll
        for (int mi = 0; mi < 4; mi++) {
            const int m = wm + mi * 16 + g;
            a[mi][0] = Ak0[(m + o0) & 127];
            a[mi][1] = Ak0[(m + 8 + o0) & 127];
            a[mi][2] = Ak4[(m + o4) & 127];
            a[mi][3] = Ak4[(m + 8 + o4) & 127];
        }
        const uint32_t* Bk0 = bufB + (ks + tig) * BSTR + wn + g;
        const uint32_t* Bk4 = bufB + (ks + tig + 4) * BSTR + wn + g;
        uint32_t b[8][2];
        #pragma unroll
        for (int ni = 0; ni < 8; ni++) { b[ni][0] = Bk0[ni * 8]; b[ni][1] = Bk4[ni * 8]; }
        #pragma unroll
        for (int mi = 0; mi < 4; mi++)
            #pragma unroll
            for (int ni = 0; ni < 8; ni++)
                mma_tf32(acc[mi][ni], a[mi], b[ni]);
    }
}

// ---------------- fused kernel ----------------
__global__ __launch_bounds__(256, 1) void fused_kernel(
    const float* __restrict__ features,
    const float* __restrict__ W_pair,
    const float* __restrict__ b_pair,
    const float* __restrict__ W_final,
    const float* __restrict__ b_final,
    const int* __restrict__ NAS,
    float* __restrict__ out)
{
    extern __shared__ uint32_t sm[];
    uint32_t* const smA = sm + OFF_AS;
    uint32_t* const smB = sm + OFF_BS;
    uint32_t* const Hs  = sm + OFF_HS;
    const uint32_t smB_addr = smem_u32(smB);

    const int tid = threadIdx.x;
    const int lane = tid & 31, wid = tid >> 5;
    const int g = lane >> 2, tig = lane & 3;
    const int wm = (wid >> 2) * 64;     // 2 m-blocks
    const int wn = (wid & 3) * 64;      // 4 n-blocks
    const int row0 = blockIdx.x * BM;

    // A loader: 128 rows x 16 k; thread -> row=tid>>1, 8 consecutive k at kc
    const int a_row = tid >> 1;            // 0..127
    const int a_kc  = (tid & 1) * 8;       // 0 or 8
    const int a_c0  = (a_row + 2 * a_kc) & 127;
    const int a_c1  = (a_c0 + 8) & 127;

    // B loader (cp.async): 16 rows x 256 floats; thread -> row=tid>>4, 64B
    const int b_row  = tid >> 4;           // 0..15
    const int b_fcol = (tid & 15) * 16;
    const uint32_t b_dst = (uint32_t)(b_row * BSTR + b_fcol) * 4u;

#define LOAD_A(Ab, kt) do { \
        const float* s_ = (Ab) + (size_t)a_row * EMBED + (kt) * 16 + a_kc; \
        av0 = *(const float4*)s_; \
        av1 = *(const float4*)(s_ + 4); \
    } while (0)
#define STORE_A(bufp) do { \
        uint32_t* d_ = (bufp) + a_kc * ASTR; \
        d_[0 * ASTR + a_c0] = f2tf(av0.x); d_[1 * ASTR + a_c0] = f2tf(av0.y); \
        d_[2 * ASTR + a_c0] = f2tf(av0.z); d_[3 * ASTR + a_c0] = f2tf(av0.w); \
        d_[4 * ASTR + a_c1] = f2tf(av1.x); d_[5 * ASTR + a_c1] = f2tf(av1.y); \
        d_[6 * ASTR + a_c1] = f2tf(av1.z); d_[7 * ASTR + a_c1] = f2tf(av1.w); \
    } while (0)
#define ISSUE_B(srcbase, buf) do { \
        const float* s_ = (srcbase) + (size_t)b_row * EMBED + b_fcol; \
        uint32_t d_ = smB_addr + (uint32_t)(buf) * (BS_BUF * 4u) + b_dst; \
        CP16(d_, s_); CP16(d_ + 16, s_ + 4); \
        CP16(d_ + 32, s_ + 8); CP16(d_ + 48, s_ + 12); \
        CP_COMMIT(); \
    } while (0)

    float acc[4][8][4];
    bool first = true;

    #pragma unroll 1
    for (int p = 0; p < PAIRS; p++) {
        if (!pair_active(p, NAS)) continue;
        const int fi = c_pi[p], fj = c_pj[p];
        const float* Ai = features + ((size_t)fi * TOKENS + row0) * EMBED;
        const float* Aj = features + ((size_t)fj * TOKENS + row0) * EMBED;
        const float* Wp = W_pair + (size_t)p * KCAT * EMBED;
        const float* Wf = W_final + (size_t)p * EMBED * EMBED;

        #pragma unroll
        for (int mi = 0; mi < 4; mi++)
            #pragma unroll
            for (int ni = 0; ni < 8; ni++)
                #pragma unroll
                for (int r = 0; r < 4; r++) acc[mi][ni][r] = 0.f;

        float4 av0, av1;

        // ---- prologue: B tiles 0,1 in flight; A tile0 -> smem; A tile1 -> regs ----
        ISSUE_B(Wp, 0);                       // group 0
        ISSUE_B(Wp + 16 * EMBED, 1);          // group 1
        LOAD_A(Ai, 0);
        STORE_A(smA);
        LOAD_A(Ai, 1);

        // ---- 48 k-tiles: stage1 (0..31, A from smA) + stage2 (32..47, A from Hs) ----
        // Invariant at top of iter t: groups 0..min(t+1, NT_ALL-1) issued.
        // wait_group 1 (or 0 on last tile) guarantees group t complete.
        #pragma unroll 1
        for (int t = 0; t < NT_ALL; t++) {
            if (t == NT_ALL - 1) { CP_WAIT0(); } else { CP_WAIT1(); }
            __syncthreads();   // B[t] visible to all; also orders smA/Hs writes from prev iter

            // issue B tile t+2 into buffer (t+2)%3 (not read or in flight) -> overlaps mma
            const int u = t + 2;
            if (u < NT_ALL) {
                const float* src = (u < NT_S1) ? (Wp + (size_t)u * 16 * EMBED)
                                               : (Wf + (size_t)(u - NT_S1) * 16 * EMBED);
                ISSUE_B(src, u % NBUF_B);
            }

            const uint32_t* bufA = (t < NT_S1) ? (smA + (t & 1) * AS_BUF)
                                               : (Hs + (t - NT_S1) * AS_BUF);
            tile_mma(bufA, smB + (t % NBUF_B) * BS_BUF, tig, g, wm, wn, acc);

            if (t + 1 < NT_S1) {
                STORE_A(smA + ((t + 1) & 1) * AS_BUF);   // next iter's barrier orders this
                if (t + 2 < NT_S1) {
                    const int u2 = t + 2;
                    const float* Ab = (u2 < 16) ? Ai : Aj;
                    LOAD_A(Ab, u2 & 15);
                }
            }

            if (t == NT_S1 - 1) {
                // ---- epilogue 1: tanh -> tf32 RN -> Hs (stage-2 A layout) ----
                // next iter's barrier orders these writes before mma reads Hs
                #pragma unroll
                for (int ni = 0; ni < 8; ni++) {
                    const int c = wn + ni * 8 + tig * 2;
                    const float2 bb = *(const float2*)&b_pair[p * EMBED + c];
                    const int sw = (c & 12) << 1;
                    #pragma unroll
                    for (int mi = 0; mi < 4; mi++) {
                        const int r0 = wm + mi * 16 + g, r1 = r0 + 8;
                        Hs[(c    ) * ASTR + ((r0 + sw) & 127)] = f2tf(fast_tanh(acc[mi][ni][0] + bb.x));
                        Hs[(c + 1) * ASTR + ((r0 + sw) & 127)] = f2tf(fast_tanh(acc[mi][ni][1] + bb.y));
                        Hs[(c    ) * ASTR + ((r1 + sw) & 127)] = f2tf(fast_tanh(acc[mi][ni][2] + bb.x));
                        Hs[(c + 1) * ASTR + ((r1 + sw) & 127)] = f2tf(fast_tanh(acc[mi][ni][3] + bb.y));
                    }
                }
                #pragma unroll
                for (int mi = 0; mi < 4; mi++)
                    #pragma unroll
                    for (int ni = 0; ni < 8; ni++)
                        #pragma unroll
                        for (int r = 0; r < 4; r++) acc[mi][ni][r] = 0.f;
            }
        }
        __syncthreads();   // protect Hs/smB before next pair overwrites

        // ---- epilogue 2 (per pair): out = / += acc (+ b_final on first) ----
        #pragma unroll
        for (int ni = 0; ni < 8; ni++) {
            const int c = wn + ni * 8 + tig * 2;
            const float2 bb = *(const float2*)&b_final[c];
            #pragma unroll
            for (int mi = 0; mi < 4; mi++) {
                const int r0 = row0 + wm + mi * 16 + g, r1 = r0 + 8;
                float2* o0 = (float2*)&out[(size_t)r0 * EMBED + c];
                float2* o1 = (float2*)&out[(size_t)r1 * EMBED + c];
                float2 v0 = make_float2(acc[mi][ni][0], acc[mi][ni][1]);
                float2 v1 = make_float2(acc[mi][ni][2], acc[mi][ni][3]);
                if (first) {
                    v0.x += bb.x; v0.y += bb.y;
                    v1.x += bb.x; v1.y += bb.y;
                } else {
                    float2 p0 = *o0, p1 = *o1;
                    v0.x += p0.x; v0.y += p0.y;
                    v1.x += p1.x; v1.y += p1.y;
                }
                *o0 = v0;
                *o1 = v1;
            }
        }
        first = false;
    }
#undef LOAD_A
#undef STORE_A
#undef ISSUE_B
}

// ---------------- launch ----------------
extern "C" void kernel_launch(void* const* d_in, const int* in_sizes, int n_in,
                              void* d_out, int out_size) {
    const float* features = (const float*)d_in[0];
    const float* W_pair   = (const float*)d_in[1];
    const float* b_pair   = (const float*)d_in[2];
    const float* W_final  = (const float*)d_in[3];
    const float* b_final  = (const float*)d_in[4];
    const int*   NAS      = (const int*)d_in[5];
    float* out = (float*)d_out;

    static int attr_set = 0;
    if (!attr_set) {
        cudaFuncSetAttribute(fused_kernel, cudaFuncAttributeMaxDynamicSharedMemorySize,
                             SMEM_BYTES);
        attr_set = 1;
    }

    fused_kernel<<<TOKENS / BM, 256, SMEM_BYTES>>>(
        features, W_pair, b_pair, W_final, b_final, NAS, out);
}